// round 3
// baseline (speedup 1.0000x reference)
#include <cuda_runtime.h>
#include <cuda_bf16.h>
#include <math.h>

#define HIDDEN 3072
#define SEQ 2048
#define NH 24
#define HD 128
#define MLPD 12288
#define W1N 21504   // 3*HIDDEN + MLPD
#define CATN 15360  // HIDDEN + MLPD
#define MODN 9216   // 3*HIDDEN

// ---------------- scratch (device globals; no allocations allowed) ----------
__device__ float d_mod[MODN];
__device__ float d_xmod[(size_t)SEQ * HIDDEN];
__device__ float d_h[(size_t)SEQ * W1N];
__device__ float d_q[(size_t)NH * SEQ * HD];
__device__ float d_k[(size_t)NH * SEQ * HD];
__device__ float d_v[(size_t)NH * SEQ * HD];
__device__ float d_s[(size_t)NH * SEQ * SEQ];
__device__ float d_cat[(size_t)SEQ * CATN];

// ---------------- packed f32x2 helpers (sm_103a FFMA2 path) -----------------
__device__ __forceinline__ unsigned long long f32x2_dup(float a) {
    unsigned long long r;
    asm("mov.b64 %0, {%1, %1};" : "=l"(r) : "f"(a));
    return r;
}
__device__ __forceinline__ unsigned long long f32x2_fma(unsigned long long a,
                                                        unsigned long long b,
                                                        unsigned long long c) {
    unsigned long long d;
    asm("fma.rn.f32x2 %0, %1, %2, %3;" : "=l"(d) : "l"(a), "l"(b), "l"(c));
    return d;
}
__device__ __forceinline__ float2 f32x2_unpack(unsigned long long v) {
    float2 f;
    asm("mov.b64 {%0, %1}, %2;" : "=f"(f.x), "=f"(f.y) : "l"(v));
    return f;
}

// ---------------- mod = silu(vec) @ mod_w + mod_b ---------------------------
__global__ void mod_gemv_kernel(const float* __restrict__ vec,
                                const float* __restrict__ mod_w,
                                const float* __restrict__ mod_b,
                                float* __restrict__ mod) {
    __shared__ float sv[HIDDEN];
    for (int i = threadIdx.x; i < HIDDEN; i += 256) {
        float v = vec[i];
        sv[i] = v / (1.0f + expf(-v));
    }
    __syncthreads();
    int j = blockIdx.x * 256 + threadIdx.x;
    const float* wp = mod_w + j;
    float acc = 0.0f;
#pragma unroll 8
    for (int k = 0; k < HIDDEN; k++) acc = fmaf(sv[k], wp[(size_t)k * MODN], acc);
    mod[j] = acc + mod_b[j];
}

// ---------------- x_mod = (1+scale)*LN(x) + shift ---------------------------
__global__ void ln_mod_kernel(const float* __restrict__ x) {
    int row = blockIdx.x;
    const float* xr = x + (size_t)row * HIDDEN;
    __shared__ float r1[256], r2[256];
    float s = 0.0f, s2 = 0.0f;
    for (int i = threadIdx.x; i < HIDDEN; i += 256) {
        float v = xr[i];
        s += v;
        s2 = fmaf(v, v, s2);
    }
    r1[threadIdx.x] = s; r2[threadIdx.x] = s2;
    __syncthreads();
    for (int o = 128; o > 0; o >>= 1) {
        if (threadIdx.x < o) { r1[threadIdx.x] += r1[threadIdx.x + o]; r2[threadIdx.x] += r2[threadIdx.x + o]; }
        __syncthreads();
    }
    float mu  = r1[0] * (1.0f / HIDDEN);
    float var = r2[0] * (1.0f / HIDDEN) - mu * mu;
    float inv = rsqrtf(var + 1e-6f);
    float* orow = d_xmod + (size_t)row * HIDDEN;
    for (int i = threadIdx.x; i < HIDDEN; i += 256) {
        float sc = 1.0f + d_mod[HIDDEN + i];
        orow[i] = (xr[i] - mu) * inv * sc + d_mod[i];
    }
}

// ---------------- generic tiled SGEMM (128x128x16, 8x8 microtile, f32x2) ----
// C = alpha * (A @ op(B)) [+ bias] [gated-residual], batched via blockIdx.z.
// mode 0: C = alpha*acc
// mode 1: C = acc + bias[n]
// mode 2: C = resid[m,n] + gate[n]*(acc + bias[n])
#define BM 128
#define BN 128
#define BK 16
#define PAD 8   // row stride BM+8 / BN+8 floats -> 544B, 16B aligned
__global__ __launch_bounds__(256) void sgemm_kernel(
    const float* __restrict__ A, int lda, long long sA,
    const float* __restrict__ B, int ldb, long long sB, int transB,
    float* __restrict__ C, int ldc, long long sC,
    int K, float alpha, int mode,
    const float* __restrict__ bias,
    const float* __restrict__ resid,
    const float* __restrict__ gate) {
    __shared__ __align__(16) float As[BK][BM + PAD];
    __shared__ __align__(16) float Bs[BK][BN + PAD];
    long long bz = blockIdx.z;
    A += bz * sA; B += bz * sB; C += bz * sC;
    const int m0 = blockIdx.y * BM, n0 = blockIdx.x * BN;
    const int tid = threadIdx.x;
    const int tx = tid & 15, ty = tid >> 4;

    // packed accumulators: acc2[i][p], p=0,1 -> cols tx*4+{01,23}; p=2,3 -> 64+tx*4+{01,23}
    unsigned long long acc2[8][4];
#pragma unroll
    for (int i = 0; i < 8; i++)
#pragma unroll
        for (int p = 0; p < 4; p++) acc2[i][p] = 0ULL;

    for (int k0 = 0; k0 < K; k0 += BK) {
#pragma unroll
        for (int t = 0; t < 2; t++) {
            int f = tid + t * 256;
            int r = f >> 2, c4 = (f & 3) << 2;
            float4 v = *reinterpret_cast<const float4*>(A + (long long)(m0 + r) * lda + k0 + c4);
            As[c4 + 0][r] = v.x; As[c4 + 1][r] = v.y; As[c4 + 2][r] = v.z; As[c4 + 3][r] = v.w;
        }
        if (transB) {
#pragma unroll
            for (int t = 0; t < 2; t++) {
                int f = tid + t * 256;
                int r = f >> 2, c4 = (f & 3) << 2;
                float4 v = *reinterpret_cast<const float4*>(B + (long long)(n0 + r) * ldb + k0 + c4);
                Bs[c4 + 0][r] = v.x; Bs[c4 + 1][r] = v.y; Bs[c4 + 2][r] = v.z; Bs[c4 + 3][r] = v.w;
            }
        } else {
#pragma unroll
            for (int t = 0; t < 2; t++) {
                int f = tid + t * 256;
                int kr = f >> 5, c4 = (f & 31) << 2;
                float4 v = *reinterpret_cast<const float4*>(B + (long long)(k0 + kr) * ldb + n0 + c4);
                *reinterpret_cast<float4*>(&Bs[kr][c4]) = v;
            }
        }
        __syncthreads();
#pragma unroll
        for (int kk = 0; kk < BK; kk++) {
            float4 a0 = *reinterpret_cast<const float4*>(&As[kk][ty * 4]);
            float4 a1 = *reinterpret_cast<const float4*>(&As[kk][64 + ty * 4]);
            ulonglong2 bl = *reinterpret_cast<const ulonglong2*>(&Bs[kk][tx * 4]);
            ulonglong2 bh = *reinterpret_cast<const ulonglong2*>(&Bs[kk][64 + tx * 4]);
            unsigned long long ad[8];
            ad[0] = f32x2_dup(a0.x); ad[1] = f32x2_dup(a0.y);
            ad[2] = f32x2_dup(a0.z); ad[3] = f32x2_dup(a0.w);
            ad[4] = f32x2_dup(a1.x); ad[5] = f32x2_dup(a1.y);
            ad[6] = f32x2_dup(a1.z); ad[7] = f32x2_dup(a1.w);
#pragma unroll
            for (int i = 0; i < 8; i++) {
                acc2[i][0] = f32x2_fma(ad[i], bl.x, acc2[i][0]);
                acc2[i][1] = f32x2_fma(ad[i], bl.y, acc2[i][1]);
                acc2[i][2] = f32x2_fma(ad[i], bh.x, acc2[i][2]);
                acc2[i][3] = f32x2_fma(ad[i], bh.y, acc2[i][3]);
            }
        }
        __syncthreads();
    }
#pragma unroll
    for (int i = 0; i < 8; i++) {
        int m = m0 + ((i < 4) ? (ty * 4 + i) : (64 + ty * 4 + i - 4));
#pragma unroll
        for (int jg = 0; jg < 2; jg++) {
            int n = n0 + jg * 64 + tx * 4;
            float2 lo = f32x2_unpack(acc2[i][jg * 2 + 0]);
            float2 hi = f32x2_unpack(acc2[i][jg * 2 + 1]);
            float4 r;
            r.x = lo.x; r.y = lo.y; r.z = hi.x; r.w = hi.y;
            if (mode == 0) {
                r.x *= alpha; r.y *= alpha; r.z *= alpha; r.w *= alpha;
            } else {
                float4 bv = *reinterpret_cast<const float4*>(bias + n);
                r.x += bv.x; r.y += bv.y; r.z += bv.z; r.w += bv.w;
                if (mode == 2) {
                    float4 gv = *reinterpret_cast<const float4*>(gate + n);
                    float4 xv = *reinterpret_cast<const float4*>(resid + (long long)m * ldc + n);
                    r.x = fmaf(gv.x, r.x, xv.x);
                    r.y = fmaf(gv.y, r.y, xv.y);
                    r.z = fmaf(gv.z, r.z, xv.z);
                    r.w = fmaf(gv.w, r.w, xv.w);
                }
            }
            *reinterpret_cast<float4*>(C + (long long)m * ldc + n) = r;
        }
    }
}

// ---------------- split qkv, RMSNorm q/k, RoPE, transpose to [h][l][d] ------
__global__ void qkv_prep_kernel(const float* __restrict__ pe,
                                const float* __restrict__ qnw,
                                const float* __restrict__ knw) {
    int wg = blockIdx.x * 8 + (threadIdx.x >> 5);
    int lane = threadIdx.x & 31;
    int l = wg / NH, hd = wg % NH;
    const float* base = d_h + (size_t)l * W1N + hd * HD + lane * 4;
    float4 qv = *reinterpret_cast<const float4*>(base);
    float4 kv = *reinterpret_cast<const float4*>(base + HIDDEN);
    float4 vv = *reinterpret_cast<const float4*>(base + 2 * HIDDEN);

    float sq = qv.x * qv.x + qv.y * qv.y + qv.z * qv.z + qv.w * qv.w;
    float sk = kv.x * kv.x + kv.y * kv.y + kv.z * kv.z + kv.w * kv.w;
#pragma unroll
    for (int o = 16; o > 0; o >>= 1) {
        sq += __shfl_xor_sync(0xffffffffu, sq, o);
        sk += __shfl_xor_sync(0xffffffffu, sk, o);
    }
    float rq = rsqrtf(sq * (1.0f / HD) + 1e-6f);
    float rk = rsqrtf(sk * (1.0f / HD) + 1e-6f);
    float4 wq = *reinterpret_cast<const float4*>(qnw + lane * 4);
    float4 wk = *reinterpret_cast<const float4*>(knw + lane * 4);
    float q0 = qv.x * rq * wq.x, q1 = qv.y * rq * wq.y, q2 = qv.z * rq * wq.z, q3 = qv.w * rq * wq.w;
    float k0 = kv.x * rk * wk.x, k1 = kv.y * rk * wk.y, k2 = kv.z * rk * wk.z, k3 = kv.w * rk * wk.w;

    const float* pep = pe + (size_t)l * 256 + lane * 8;
    float4 p0 = *reinterpret_cast<const float4*>(pep);
    float4 p1 = *reinterpret_cast<const float4*>(pep + 4);
    float4 qo, ko;
    qo.x = p0.x * q0 + p0.y * q1;  qo.y = p0.z * q0 + p0.w * q1;
    qo.z = p1.x * q2 + p1.y * q3;  qo.w = p1.z * q2 + p1.w * q3;
    ko.x = p0.x * k0 + p0.y * k1;  ko.y = p0.z * k0 + p0.w * k1;
    ko.z = p1.x * k2 + p1.y * k3;  ko.w = p1.z * k2 + p1.w * k3;

    size_t o = ((size_t)hd * SEQ + l) * HD + lane * 4;
    *reinterpret_cast<float4*>(d_q + o) = qo;
    *reinterpret_cast<float4*>(d_k + o) = ko;
    *reinterpret_cast<float4*>(d_v + o) = vv;
}

// ---------------- row softmax over d_s ( NH*SEQ rows of SEQ ) ---------------
__global__ void softmax_kernel() {
    float* row = d_s + (size_t)blockIdx.x * SEQ;
    int tid = threadIdx.x;
    float v[8];
    float m = -1e30f;
#pragma unroll
    for (int j = 0; j < 8; j++) { v[j] = row[tid + j * 256]; m = fmaxf(m, v[j]); }
    __shared__ float red[256];
    red[tid] = m;
    __syncthreads();
    for (int o = 128; o > 0; o >>= 1) {
        if (tid < o) red[tid] = fmaxf(red[tid], red[tid + o]);
        __syncthreads();
    }
    m = red[0];
    __syncthreads();
    float s = 0.0f;
#pragma unroll
    for (int j = 0; j < 8; j++) { v[j] = __expf(v[j] - m); s += v[j]; }
    red[tid] = s;
    __syncthreads();
    for (int o = 128; o > 0; o >>= 1) {
        if (tid < o) red[tid] += red[tid + o];
        __syncthreads();
    }
    float inv = 1.0f / red[0];
#pragma unroll
    for (int j = 0; j < 8; j++) row[tid + j * 256] = v[j] * inv;
}

// ---------------- gelu(mlp half of h) -> cat[:, HIDDEN:] --------------------
__global__ void gelu_kernel() {
    size_t g = (size_t)blockIdx.x * 256 + threadIdx.x;  // total SEQ*MLPD
    size_t r = g / MLPD;
    int j = (int)(g % MLPD);
    float xv = d_h[r * W1N + 3 * HIDDEN + j];
    float t = tanhf(0.7978845608028654f * (xv + 0.044715f * xv * xv * xv));
    d_cat[r * CATN + HIDDEN + j] = 0.5f * xv * (1.0f + t);
}

// ---------------- driver ----------------------------------------------------
extern "C" void kernel_launch(void* const* d_in, const int* in_sizes, int n_in,
                              void* d_out, int out_size) {
    const float* x     = (const float*)d_in[0];
    const float* vec   = (const float*)d_in[1];
    const float* pe    = (const float*)d_in[2];
    const float* w1    = (const float*)d_in[3];
    const float* b1    = (const float*)d_in[4];
    const float* w2    = (const float*)d_in[5];
    const float* b2    = (const float*)d_in[6];
    const float* mod_w = (const float*)d_in[7];
    const float* mod_b = (const float*)d_in[8];
    const float* qnw   = (const float*)d_in[9];
    const float* knw   = (const float*)d_in[10];
    float* out = (float*)d_out;

    float *p_mod, *p_xmod, *p_h, *p_q, *p_k, *p_v, *p_s, *p_cat;
    cudaGetSymbolAddress((void**)&p_mod,  d_mod);
    cudaGetSymbolAddress((void**)&p_xmod, d_xmod);
    cudaGetSymbolAddress((void**)&p_h,    d_h);
    cudaGetSymbolAddress((void**)&p_q,    d_q);
    cudaGetSymbolAddress((void**)&p_k,    d_k);
    cudaGetSymbolAddress((void**)&p_v,    d_v);
    cudaGetSymbolAddress((void**)&p_s,    d_s);
    cudaGetSymbolAddress((void**)&p_cat,  d_cat);

    // 1) modulation vector
    mod_gemv_kernel<<<MODN / 256, 256>>>(vec, mod_w, mod_b, p_mod);
    // 2) LN + modulate
    ln_mod_kernel<<<SEQ, 256>>>(x);
    // 3) h = x_mod @ w1 + b1
    sgemm_kernel<<<dim3(W1N / BN, SEQ / BM, 1), 256>>>(
        p_xmod, HIDDEN, 0, w1, W1N, 0, 0, p_h, W1N, 0,
        HIDDEN, 1.0f, 1, b1, nullptr, nullptr);
    // 4) split qkv, rmsnorm, rope
    qkv_prep_kernel<<<SEQ * NH / 8, 256>>>(pe, qnw, knw);
    // 5) scores = (q @ k^T) * sc     (batched over heads, NT)
    sgemm_kernel<<<dim3(SEQ / BN, SEQ / BM, NH), 256>>>(
        p_q, HD, (long long)SEQ * HD, p_k, HD, (long long)SEQ * HD, 1,
        p_s, SEQ, (long long)SEQ * SEQ,
        HD, 0.08838834764831845f, 0, nullptr, nullptr, nullptr);
    // 6) softmax rows
    softmax_kernel<<<NH * SEQ, 256>>>();
    // 7) attn = probs @ v -> cat[:, :HIDDEN] (head-interleaved columns)
    sgemm_kernel<<<dim3(HD / BN, SEQ / BM, NH), 256>>>(
        p_s, SEQ, (long long)SEQ * SEQ, p_v, HD, (long long)SEQ * HD, 0,
        p_cat, CATN, HD,
        SEQ, 1.0f, 0, nullptr, nullptr, nullptr);
    // 8) gelu(mlp) -> cat[:, HIDDEN:]
    gelu_kernel<<<(SEQ * MLPD) / 256, 256>>>();
    // 9) out = x + gate * (cat @ w2 + b2)
    sgemm_kernel<<<dim3(HIDDEN / BN, SEQ / BM, 1), 256>>>(
        p_cat, CATN, 0, w2, HIDDEN, 0, 0, out, HIDDEN, 0,
        CATN, 1.0f, 2, b2, x, p_mod + 2 * HIDDEN);
}

// round 7
// speedup vs baseline: 2.2142x; 2.2142x over previous
#include <cuda_runtime.h>
#include <cuda_bf16.h>
#include <math.h>
#include <stdint.h>

#define HIDDEN 3072
#define SEQ 2048
#define NH 24
#define HD 128
#define MLPD 12288
#define W1N 21504   // 3*HIDDEN + MLPD
#define CATN 15360  // HIDDEN + MLPD
#define MODN 9216   // 3*HIDDEN

// ---------------- scratch (device globals; no allocations allowed) ----------
__device__ float d_mod[MODN];
__device__ float d_xmod[(size_t)SEQ * HIDDEN];
__device__ float d_h[(size_t)SEQ * W1N];
__device__ float d_q[(size_t)NH * SEQ * HD];
__device__ float d_k[(size_t)NH * SEQ * HD];
__device__ float d_v[(size_t)NH * SEQ * HD];
__device__ float d_s[(size_t)NH * SEQ * SEQ];
__device__ float d_cat[(size_t)SEQ * CATN];
// bf16 split operands (16B aligned for vector access)
__device__ __align__(16) __nv_bfloat16 d_a1h[(size_t)SEQ * HIDDEN];
__device__ __align__(16) __nv_bfloat16 d_a1l[(size_t)SEQ * HIDDEN];
__device__ __align__(16) __nv_bfloat16 d_a2h[(size_t)SEQ * CATN];
__device__ __align__(16) __nv_bfloat16 d_a2l[(size_t)SEQ * CATN];
__device__ __align__(16) __nv_bfloat16 d_w1th[(size_t)W1N * HIDDEN];  // [N=W1N, K=HIDDEN]
__device__ __align__(16) __nv_bfloat16 d_w1tl[(size_t)W1N * HIDDEN];
__device__ __align__(16) __nv_bfloat16 d_w2th[(size_t)HIDDEN * CATN]; // [N=HIDDEN, K=CATN]
__device__ __align__(16) __nv_bfloat16 d_w2tl[(size_t)HIDDEN * CATN];

// =================== mma.sync bf16 16x8x16 ==================================
__device__ __forceinline__ void mma16816(float* d, const uint32_t* a, const uint32_t* b) {
    asm volatile(
        "mma.sync.aligned.m16n8k16.row.col.f32.bf16.bf16.f32 "
        "{%0,%1,%2,%3}, {%4,%5,%6,%7}, {%8,%9}, {%0,%1,%2,%3};"
        : "+f"(d[0]), "+f"(d[1]), "+f"(d[2]), "+f"(d[3])
        : "r"(a[0]), "r"(a[1]), "r"(a[2]), "r"(a[3]), "r"(b[0]), "r"(b[1]));
}

// =================== HMMA GEMM: C[M,N] = A[M,K] @ B^T (B:[N,K]) =============
// bf16 split-3: Ah*Bh + Al*Bh + Ah*Bl, fp32 accumulate.
// Tile 128x128, KC=32. mode 1: C=acc+bias; mode 2: C=resid+gate*(acc+bias)
#define KC 32
#define TSTR 40   // padded k-stride (bf16 elems); 80B rows -> 16B-aligned float4 stores
__global__ __launch_bounds__(256, 2) void hmma_gemm_kernel(
    const __nv_bfloat16* __restrict__ Ah, const __nv_bfloat16* __restrict__ Al,
    const __nv_bfloat16* __restrict__ Bh, const __nv_bfloat16* __restrict__ Bl,
    float* __restrict__ C, int ldc, int K, int mode,
    const float* __restrict__ bias,
    const float* __restrict__ resid,
    const float* __restrict__ gate) {
    __shared__ __align__(16) __nv_bfloat16 sAh[128 * TSTR];
    __shared__ __align__(16) __nv_bfloat16 sAl[128 * TSTR];
    __shared__ __align__(16) __nv_bfloat16 sBh[128 * TSTR];
    __shared__ __align__(16) __nv_bfloat16 sBl[128 * TSTR];

    const int tid = threadIdx.x;
    const int wid = tid >> 5, lane = tid & 31;
    const int m0 = blockIdx.x * 128, n0 = blockIdx.y * 128;
    const int wm = (wid >> 2) * 64, wn = (wid & 3) * 32;

    float acc[4][4][4];
#pragma unroll
    for (int mt = 0; mt < 4; mt++)
#pragma unroll
        for (int nt = 0; nt < 4; nt++)
#pragma unroll
            for (int r = 0; r < 4; r++) acc[mt][nt][r] = 0.0f;

    const int lr = tid >> 2;          // 0..63
    const int lc = (tid & 3) * 8;     // 0,8,16,24 (bf16 elems, 16B chunks)

    for (int kc = 0; kc < K; kc += KC) {
#pragma unroll
        for (int i = 0; i < 2; i++) {
            int row = lr + i * 64;
            *(float4*)&sAh[row * TSTR + lc] = *(const float4*)(Ah + (size_t)(m0 + row) * K + kc + lc);
            *(float4*)&sAl[row * TSTR + lc] = *(const float4*)(Al + (size_t)(m0 + row) * K + kc + lc);
            *(float4*)&sBh[row * TSTR + lc] = *(const float4*)(Bh + (size_t)(n0 + row) * K + kc + lc);
            *(float4*)&sBl[row * TSTR + lc] = *(const float4*)(Bl + (size_t)(n0 + row) * K + kc + lc);
        }
        __syncthreads();

#pragma unroll
        for (int ks = 0; ks < 2; ks++) {
            const int k0 = ks * 16;
            const int ar = lane >> 2, ak = (lane & 3) * 2;
            uint32_t ah[4][4], bh[4][2], xl[4][4];  // xl reused for al then bl
            // A-hi frags
#pragma unroll
            for (int mt = 0; mt < 4; mt++) {
                int base = (wm + mt * 16 + ar) * TSTR + k0 + ak;
                ah[mt][0] = *(const uint32_t*)&sAh[base];
                ah[mt][1] = *(const uint32_t*)&sAh[base + 8 * TSTR];
                ah[mt][2] = *(const uint32_t*)&sAh[base + 8];
                ah[mt][3] = *(const uint32_t*)&sAh[base + 8 * TSTR + 8];
            }
            // B-hi frags
#pragma unroll
            for (int nt = 0; nt < 4; nt++) {
                int base = (wn + nt * 8 + ar) * TSTR + k0 + ak;
                bh[nt][0] = *(const uint32_t*)&sBh[base];
                bh[nt][1] = *(const uint32_t*)&sBh[base + 8];
            }
            // Ah * Bh
#pragma unroll
            for (int mt = 0; mt < 4; mt++)
#pragma unroll
                for (int nt = 0; nt < 4; nt++) mma16816(acc[mt][nt], ah[mt], bh[nt]);
            // A-lo frags; Al * Bh
#pragma unroll
            for (int mt = 0; mt < 4; mt++) {
                int base = (wm + mt * 16 + ar) * TSTR + k0 + ak;
                xl[mt][0] = *(const uint32_t*)&sAl[base];
                xl[mt][1] = *(const uint32_t*)&sAl[base + 8 * TSTR];
                xl[mt][2] = *(const uint32_t*)&sAl[base + 8];
                xl[mt][3] = *(const uint32_t*)&sAl[base + 8 * TSTR + 8];
            }
#pragma unroll
            for (int mt = 0; mt < 4; mt++)
#pragma unroll
                for (int nt = 0; nt < 4; nt++) mma16816(acc[mt][nt], xl[mt], bh[nt]);
            // B-lo frags; Ah * Bl
            uint32_t bl[4][2];
#pragma unroll
            for (int nt = 0; nt < 4; nt++) {
                int base = (wn + nt * 8 + ar) * TSTR + k0 + ak;
                bl[nt][0] = *(const uint32_t*)&sBl[base];
                bl[nt][1] = *(const uint32_t*)&sBl[base + 8];
            }
#pragma unroll
            for (int mt = 0; mt < 4; mt++)
#pragma unroll
                for (int nt = 0; nt < 4; nt++) mma16816(acc[mt][nt], ah[mt], bl[nt]);
        }
        __syncthreads();
    }

    // epilogue: fused bias / gated-residual, direct register->gmem stores
#pragma unroll
    for (int mt = 0; mt < 4; mt++) {
#pragma unroll
        for (int h = 0; h < 2; h++) {
            long long m = m0 + wm + mt * 16 + (lane >> 2) + h * 8;
#pragma unroll
            for (int nt = 0; nt < 4; nt++) {
                int n = n0 + wn + nt * 8 + (lane & 3) * 2;
                float vx = acc[mt][nt][h * 2 + 0] + bias[n];
                float vy = acc[mt][nt][h * 2 + 1] + bias[n + 1];
                if (mode == 2) {
                    float2 xv = *(const float2*)(resid + m * ldc + n);
                    vx = fmaf(gate[n],     vx, xv.x);
                    vy = fmaf(gate[n + 1], vy, xv.y);
                }
                float2 o; o.x = vx; o.y = vy;
                *(float2*)(C + m * ldc + n) = o;
            }
        }
    }
}

// =================== split / transpose prep kernels =========================
__global__ void split_kernel(const float* __restrict__ src,
                             __nv_bfloat16* __restrict__ dh,
                             __nv_bfloat16* __restrict__ dl) {
    size_t i = ((size_t)blockIdx.x * 256 + threadIdx.x) * 4;
    float4 v = *(const float4*)(src + i);
    __nv_bfloat16 h0 = __float2bfloat16(v.x), h1 = __float2bfloat16(v.y);
    __nv_bfloat16 h2 = __float2bfloat16(v.z), h3 = __float2bfloat16(v.w);
    __nv_bfloat162 hA, hB, lA, lB;
    hA.x = h0; hA.y = h1; hB.x = h2; hB.y = h3;
    lA.x = __float2bfloat16(v.x - __bfloat162float(h0));
    lA.y = __float2bfloat16(v.y - __bfloat162float(h1));
    lB.x = __float2bfloat16(v.z - __bfloat162float(h2));
    lB.y = __float2bfloat16(v.w - __bfloat162float(h3));
    uint2 uh, ul;
    uh.x = *(uint32_t*)&hA; uh.y = *(uint32_t*)&hB;
    ul.x = *(uint32_t*)&lA; ul.y = *(uint32_t*)&lB;
    *(uint2*)(dh + i) = uh;
    *(uint2*)(dl + i) = ul;
}

// src fp32 [R, Cc] -> dh/dl bf16 [Cc, R] (transposed, split)
__global__ void transpose_split_kernel(const float* __restrict__ src, int R, int Cc,
                                       __nv_bfloat16* __restrict__ dh,
                                       __nv_bfloat16* __restrict__ dl) {
    __shared__ float t[32][33];
    int c0 = blockIdx.x * 32, r0 = blockIdx.y * 32;
    int tx = threadIdx.x, ty = threadIdx.y;
#pragma unroll
    for (int i = 0; i < 4; i++)
        t[ty + 8 * i][tx] = src[(size_t)(r0 + ty + 8 * i) * Cc + c0 + tx];
    __syncthreads();
#pragma unroll
    for (int i = 0; i < 4; i++) {
        float v = t[tx][ty + 8 * i];
        __nv_bfloat16 h = __float2bfloat16(v);
        size_t o = (size_t)(c0 + ty + 8 * i) * R + r0 + tx;
        dh[o] = h;
        dl[o] = __float2bfloat16(v - __bfloat162float(h));
    }
}

// =================== small kernels =========================================
__global__ void mod_gemv_kernel(const float* __restrict__ vec,
                                const float* __restrict__ mod_w,
                                const float* __restrict__ mod_b,
                                float* __restrict__ mod) {
    __shared__ float sv[HIDDEN];
    for (int i = threadIdx.x; i < HIDDEN; i += 256) {
        float v = vec[i];
        sv[i] = v / (1.0f + expf(-v));
    }
    __syncthreads();
    int j = blockIdx.x * 256 + threadIdx.x;
    const float* wp = mod_w + j;
    float acc = 0.0f;
#pragma unroll 8
    for (int k = 0; k < HIDDEN; k++) acc = fmaf(sv[k], wp[(size_t)k * MODN], acc);
    mod[j] = acc + mod_b[j];
}

__global__ void ln_mod_kernel(const float* __restrict__ x) {
    int row = blockIdx.x;
    const float* xr = x + (size_t)row * HIDDEN;
    __shared__ float r1[256], r2[256];
    float s = 0.0f, s2 = 0.0f;
    for (int i = threadIdx.x; i < HIDDEN; i += 256) {
        float v = xr[i];
        s += v;
        s2 = fmaf(v, v, s2);
    }
    r1[threadIdx.x] = s; r2[threadIdx.x] = s2;
    __syncthreads();
    for (int o = 128; o > 0; o >>= 1) {
        if (threadIdx.x < o) { r1[threadIdx.x] += r1[threadIdx.x + o]; r2[threadIdx.x] += r2[threadIdx.x + o]; }
        __syncthreads();
    }
    float mu  = r1[0] * (1.0f / HIDDEN);
    float var = r2[0] * (1.0f / HIDDEN) - mu * mu;
    float inv = rsqrtf(var + 1e-6f);
    float* orow = d_xmod + (size_t)row * HIDDEN;
    for (int i = threadIdx.x; i < HIDDEN; i += 256) {
        float sc = 1.0f + d_mod[HIDDEN + i];
        orow[i] = (xr[i] - mu) * inv * sc + d_mod[i];
    }
}

// ---------------- SIMT SGEMM (round-1 version) for attention ----------------
#define BM 128
#define BN 128
#define BK 16
__global__ __launch_bounds__(256) void sgemm_kernel(
    const float* __restrict__ A, int lda, long long sA,
    const float* __restrict__ B, int ldb, long long sB, int transB,
    float* __restrict__ C, int ldc, long long sC,
    int K, float alpha) {
    __shared__ float As[BK][BM + 4];
    __shared__ float Bs[BK][BN + 4];
    long long bz = blockIdx.z;
    A += bz * sA; B += bz * sB; C += bz * sC;
    const int m0 = blockIdx.y * BM, n0 = blockIdx.x * BN;
    const int tid = threadIdx.x;
    const int tx = tid & 15, ty = tid >> 4;
    float acc[8][8];
#pragma unroll
    for (int i = 0; i < 8; i++)
#pragma unroll
        for (int j = 0; j < 8; j++) acc[i][j] = 0.0f;

    for (int k0 = 0; k0 < K; k0 += BK) {
#pragma unroll
        for (int t = 0; t < 2; t++) {
            int f = tid + t * 256;
            int r = f >> 2, c4 = (f & 3) << 2;
            float4 v = *reinterpret_cast<const float4*>(A + (long long)(m0 + r) * lda + k0 + c4);
            As[c4 + 0][r] = v.x; As[c4 + 1][r] = v.y; As[c4 + 2][r] = v.z; As[c4 + 3][r] = v.w;
        }
        if (transB) {
#pragma unroll
            for (int t = 0; t < 2; t++) {
                int f = tid + t * 256;
                int r = f >> 2, c4 = (f & 3) << 2;
                float4 v = *reinterpret_cast<const float4*>(B + (long long)(n0 + r) * ldb + k0 + c4);
                Bs[c4 + 0][r] = v.x; Bs[c4 + 1][r] = v.y; Bs[c4 + 2][r] = v.z; Bs[c4 + 3][r] = v.w;
            }
        } else {
#pragma unroll
            for (int t = 0; t < 2; t++) {
                int f = tid + t * 256;
                int kr = f >> 5, c4 = (f & 31) << 2;
                float4 v = *reinterpret_cast<const float4*>(B + (long long)(k0 + kr) * ldb + n0 + c4);
                *reinterpret_cast<float4*>(&Bs[kr][c4]) = v;
            }
        }
        __syncthreads();
#pragma unroll
        for (int kk = 0; kk < BK; kk++) {
            float a[8], b[8];
            *reinterpret_cast<float4*>(a)     = *reinterpret_cast<const float4*>(&As[kk][ty * 4]);
            *reinterpret_cast<float4*>(a + 4) = *reinterpret_cast<const float4*>(&As[kk][64 + ty * 4]);
            *reinterpret_cast<float4*>(b)     = *reinterpret_cast<const float4*>(&Bs[kk][tx * 4]);
            *reinterpret_cast<float4*>(b + 4) = *reinterpret_cast<const float4*>(&Bs[kk][64 + tx * 4]);
#pragma unroll
            for (int i = 0; i < 8; i++)
#pragma unroll
                for (int j = 0; j < 8; j++) acc[i][j] = fmaf(a[i], b[j], acc[i][j]);
        }
        __syncthreads();
    }
#pragma unroll
    for (int i = 0; i < 8; i++) {
        int m = m0 + ((i < 4) ? (ty * 4 + i) : (64 + ty * 4 + i - 4));
#pragma unroll
        for (int jg = 0; jg < 2; jg++) {
            int n = n0 + jg * 64 + tx * 4;
            float4 r;
            r.x = acc[i][jg * 4 + 0] * alpha; r.y = acc[i][jg * 4 + 1] * alpha;
            r.z = acc[i][jg * 4 + 2] * alpha; r.w = acc[i][jg * 4 + 3] * alpha;
            *reinterpret_cast<float4*>(C + (long long)m * ldc + n) = r;
        }
    }
}

__global__ void qkv_prep_kernel(const float* __restrict__ pe,
                                const float* __restrict__ qnw,
                                const float* __restrict__ knw) {
    int wg = blockIdx.x * 8 + (threadIdx.x >> 5);
    int lane = threadIdx.x & 31;
    int l = wg / NH, hd = wg % NH;
    const float* base = d_h + (size_t)l * W1N + hd * HD + lane * 4;
    float4 qv = *reinterpret_cast<const float4*>(base);
    float4 kv = *reinterpret_cast<const float4*>(base + HIDDEN);
    float4 vv = *reinterpret_cast<const float4*>(base + 2 * HIDDEN);

    float sq = qv.x * qv.x + qv.y * qv.y + qv.z * qv.z + qv.w * qv.w;
    float sk = kv.x * kv.x + kv.y * kv.y + kv.z * kv.z + kv.w * kv.w;
#pragma unroll
    for (int o = 16; o > 0; o >>= 1) {
        sq += __shfl_xor_sync(0xffffffffu, sq, o);
        sk += __shfl_xor_sync(0xffffffffu, sk, o);
    }
    float rq = rsqrtf(sq * (1.0f / HD) + 1e-6f);
    float rk = rsqrtf(sk * (1.0f / HD) + 1e-6f);
    float4 wq = *reinterpret_cast<const float4*>(qnw + lane * 4);
    float4 wk = *reinterpret_cast<const float4*>(knw + lane * 4);
    float q0 = qv.x * rq * wq.x, q1 = qv.y * rq * wq.y, q2 = qv.z * rq * wq.z, q3 = qv.w * rq * wq.w;
    float k0 = kv.x * rk * wk.x, k1 = kv.y * rk * wk.y, k2 = kv.z * rk * wk.z, k3 = kv.w * rk * wk.w;

    const float* pep = pe + (size_t)l * 256 + lane * 8;
    float4 p0 = *reinterpret_cast<const float4*>(pep);
    float4 p1 = *reinterpret_cast<const float4*>(pep + 4);
    float4 qo, ko;
    qo.x = p0.x * q0 + p0.y * q1;  qo.y = p0.z * q0 + p0.w * q1;
    qo.z = p1.x * q2 + p1.y * q3;  qo.w = p1.z * q2 + p1.w * q3;
    ko.x = p0.x * k0 + p0.y * k1;  ko.y = p0.z * k0 + p0.w * k1;
    ko.z = p1.x * k2 + p1.y * k3;  ko.w = p1.z * k2 + p1.w * k3;

    size_t o = ((size_t)hd * SEQ + l) * HD + lane * 4;
    *reinterpret_cast<float4*>(d_q + o) = qo;
    *reinterpret_cast<float4*>(d_k + o) = ko;
    *reinterpret_cast<float4*>(d_v + o) = vv;
}

__global__ void softmax_kernel() {
    float* row = d_s + (size_t)blockIdx.x * SEQ;
    int tid = threadIdx.x;
    float v[8];
    float m = -1e30f;
#pragma unroll
    for (int j = 0; j < 8; j++) { v[j] = row[tid + j * 256]; m = fmaxf(m, v[j]); }
    __shared__ float red[256];
    red[tid] = m;
    __syncthreads();
    for (int o = 128; o > 0; o >>= 1) {
        if (tid < o) red[tid] = fmaxf(red[tid], red[tid + o]);
        __syncthreads();
    }
    m = red[0];
    __syncthreads();
    float s = 0.0f;
#pragma unroll
    for (int j = 0; j < 8; j++) { v[j] = __expf(v[j] - m); s += v[j]; }
    red[tid] = s;
    __syncthreads();
    for (int o = 128; o > 0; o >>= 1) {
        if (tid < o) red[tid] += red[tid + o];
        __syncthreads();
    }
    float inv = 1.0f / red[0];
#pragma unroll
    for (int j = 0; j < 8; j++) row[tid + j * 256] = v[j] * inv;
}

__global__ void gelu_kernel() {
    size_t g = (size_t)blockIdx.x * 256 + threadIdx.x;
    size_t r = g / MLPD;
    int j = (int)(g % MLPD);
    float xv = d_h[r * W1N + 3 * HIDDEN + j];
    float t = tanhf(0.7978845608028654f * (xv + 0.044715f * xv * xv * xv));
    d_cat[r * CATN + HIDDEN + j] = 0.5f * xv * (1.0f + t);
}

// =================== driver =================================================
extern "C" void kernel_launch(void* const* d_in, const int* in_sizes, int n_in,
                              void* d_out, int out_size) {
    const float* x     = (const float*)d_in[0];
    const float* vec   = (const float*)d_in[1];
    const float* pe    = (const float*)d_in[2];
    const float* w1    = (const float*)d_in[3];
    const float* b1    = (const float*)d_in[4];
    const float* w2    = (const float*)d_in[5];
    const float* b2    = (const float*)d_in[6];
    const float* mod_w = (const float*)d_in[7];
    const float* mod_b = (const float*)d_in[8];
    const float* qnw   = (const float*)d_in[9];
    const float* knw   = (const float*)d_in[10];
    float* out = (float*)d_out;

    float *p_mod, *p_xmod, *p_h, *p_q, *p_k, *p_v, *p_s, *p_cat;
    __nv_bfloat16 *p_a1h, *p_a1l, *p_a2h, *p_a2l, *p_w1th, *p_w1tl, *p_w2th, *p_w2tl;
    cudaGetSymbolAddress((void**)&p_mod,  d_mod);
    cudaGetSymbolAddress((void**)&p_xmod, d_xmod);
    cudaGetSymbolAddress((void**)&p_h,    d_h);
    cudaGetSymbolAddress((void**)&p_q,    d_q);
    cudaGetSymbolAddress((void**)&p_k,    d_k);
    cudaGetSymbolAddress((void**)&p_v,    d_v);
    cudaGetSymbolAddress((void**)&p_s,    d_s);
    cudaGetSymbolAddress((void**)&p_cat,  d_cat);
    cudaGetSymbolAddress((void**)&p_a1h,  d_a1h);
    cudaGetSymbolAddress((void**)&p_a1l,  d_a1l);
    cudaGetSymbolAddress((void**)&p_a2h,  d_a2h);
    cudaGetSymbolAddress((void**)&p_a2l,  d_a2l);
    cudaGetSymbolAddress((void**)&p_w1th, d_w1th);
    cudaGetSymbolAddress((void**)&p_w1tl, d_w1tl);
    cudaGetSymbolAddress((void**)&p_w2th, d_w2th);
    cudaGetSymbolAddress((void**)&p_w2tl, d_w2tl);

    // 1) modulation + LN
    mod_gemv_kernel<<<MODN / 256, 256>>>(vec, mod_w, mod_b, p_mod);
    ln_mod_kernel<<<SEQ, 256>>>(x);
    // 2) operand prep for GEMM1
    split_kernel<<<(SEQ * HIDDEN) / 1024, 256>>>(p_xmod, p_a1h, p_a1l);
    transpose_split_kernel<<<dim3(W1N / 32, HIDDEN / 32), dim3(32, 8)>>>(w1, HIDDEN, W1N, p_w1th, p_w1tl);
    // 3) GEMM1: h = x_mod @ w1 + b1  (HMMA split-3)
    hmma_gemm_kernel<<<dim3(SEQ / 128, W1N / 128), 256>>>(
        p_a1h, p_a1l, p_w1th, p_w1tl, p_h, W1N, HIDDEN, 1, b1, nullptr, nullptr);
    // 4) qkv prep
    qkv_prep_kernel<<<SEQ * NH / 8, 256>>>(pe, qnw, knw);
    // 5) scores = (q @ k^T) * sc
    sgemm_kernel<<<dim3(SEQ / BN, SEQ / BM, NH), 256>>>(
        p_q, HD, (long long)SEQ * HD, p_k, HD, (long long)SEQ * HD, 1,
        p_s, SEQ, (long long)SEQ * SEQ, HD, 0.08838834764831845f);
    // 6) softmax
    softmax_kernel<<<NH * SEQ, 256>>>();
    // 7) attn = probs @ v -> cat[:, :HIDDEN]
    sgemm_kernel<<<dim3(HD / BN, SEQ / BM, NH), 256>>>(
        p_s, SEQ, (long long)SEQ * SEQ, p_v, HD, (long long)SEQ * HD, 0,
        p_cat, CATN, HD, SEQ, 1.0f);
    // 8) gelu -> cat[:, HIDDEN:]
    gelu_kernel<<<(SEQ * MLPD) / 256, 256>>>();
    // 9) operand prep for GEMM2
    split_kernel<<<(SEQ * CATN) / 1024, 256>>>(p_cat, p_a2h, p_a2l);
    transpose_split_kernel<<<dim3(HIDDEN / 32, CATN / 32), dim3(32, 8)>>>(w2, CATN, HIDDEN, p_w2th, p_w2tl);
    // 10) GEMM2: out = x + gate * (cat @ w2 + b2)  (HMMA split-3)
    hmma_gemm_kernel<<<dim3(SEQ / 128, HIDDEN / 128), 256>>>(
        p_a2h, p_a2l, p_w2th, p_w2tl, out, HIDDEN, CATN, 2, b2, x, p_mod + 2 * HIDDEN);
}

// round 10
// speedup vs baseline: 2.6037x; 1.1759x over previous
#include <cuda_runtime.h>
#include <cuda_bf16.h>
#include <math.h>
#include <stdint.h>

#define HIDDEN 3072
#define SEQ 2048
#define NH 24
#define HD 128
#define MLPD 12288
#define W1N 21504   // 3*HIDDEN + MLPD
#define CATN 15360  // HIDDEN + MLPD
#define MODN 9216   // 3*HIDDEN

// ---------------- scratch (device globals; no allocations allowed) ----------
__device__ float d_mod[MODN];
__device__ float d_xmod[(size_t)SEQ * HIDDEN];
__device__ float d_h[(size_t)SEQ * W1N];
__device__ float d_v[(size_t)NH * SEQ * HD];
__device__ float d_s[(size_t)NH * SEQ * SEQ];
// bf16 split operands (16B aligned for vector access)
__device__ __align__(16) __nv_bfloat16 d_a1h[(size_t)SEQ * HIDDEN];
__device__ __align__(16) __nv_bfloat16 d_a1l[(size_t)SEQ * HIDDEN];
__device__ __align__(16) __nv_bfloat16 d_a2h[(size_t)SEQ * CATN];
__device__ __align__(16) __nv_bfloat16 d_a2l[(size_t)SEQ * CATN];
__device__ __align__(16) __nv_bfloat16 d_w1th[(size_t)W1N * HIDDEN];  // [N=W1N, K=HIDDEN]
__device__ __align__(16) __nv_bfloat16 d_w1tl[(size_t)W1N * HIDDEN];
__device__ __align__(16) __nv_bfloat16 d_w2th[(size_t)HIDDEN * CATN]; // [N=HIDDEN, K=CATN]
__device__ __align__(16) __nv_bfloat16 d_w2tl[(size_t)HIDDEN * CATN];
// attention bf16 split operands
__device__ __align__(16) __nv_bfloat16 d_qh[(size_t)NH * SEQ * HD];
__device__ __align__(16) __nv_bfloat16 d_ql[(size_t)NH * SEQ * HD];
__device__ __align__(16) __nv_bfloat16 d_kh[(size_t)NH * SEQ * HD];
__device__ __align__(16) __nv_bfloat16 d_kl[(size_t)NH * SEQ * HD];
__device__ __align__(16) __nv_bfloat16 d_vth[(size_t)NH * HD * SEQ];
__device__ __align__(16) __nv_bfloat16 d_vtl[(size_t)NH * HD * SEQ];
__device__ __align__(16) __nv_bfloat16 d_sh[(size_t)NH * SEQ * SEQ];
__device__ __align__(16) __nv_bfloat16 d_sl[(size_t)NH * SEQ * SEQ];

// =================== helpers ================================================
__device__ __forceinline__ uint32_t smem_u32(const void* p) {
    uint32_t a;
    asm("{ .reg .u64 t; cvta.to.shared.u64 t, %1; cvt.u32.u64 %0, t; }" : "=r"(a) : "l"(p));
    return a;
}
__device__ __forceinline__ void cp_async16(void* sdst, const void* gsrc) {
    asm volatile("cp.async.cg.shared.global [%0], [%1], 16;"
                 :: "r"(smem_u32(sdst)), "l"(gsrc) : "memory");
}
__device__ __forceinline__ void mma16816(float* d, const uint32_t* a, const uint32_t* b) {
    asm volatile(
        "mma.sync.aligned.m16n8k16.row.col.f32.bf16.bf16.f32 "
        "{%0,%1,%2,%3}, {%4,%5,%6,%7}, {%8,%9}, {%0,%1,%2,%3};"
        : "+f"(d[0]), "+f"(d[1]), "+f"(d[2]), "+f"(d[3])
        : "r"(a[0]), "r"(a[1]), "r"(a[2]), "r"(a[3]), "r"(b[0]), "r"(b[1]));
}

// =================== HMMA GEMM: C[M,N] = A[M,K] @ B^T (B:[N,K]) =============
// bf16 split-3: Ah*Bh + Al*Bh + Ah*Bl, fp32 accumulate. Double-buffered cp.async.
// mode 0: C = alpha*acc
// mode 1: C = acc + bias
// mode 2: C = resid + gate*(acc + bias)
// mode 3: split(acc) -> outH/outL bf16
#define KC 32
#define TSTR 40                      // padded k-stride; 80B rows, 16B aligned
#define TILE_ELEMS (128 * TSTR)      // 5120 bf16 = 10240 B
#define STAGE_ELEMS (4 * TILE_ELEMS)
#define HMMA_SMEM_BYTES (2 * STAGE_ELEMS * 2)  // 81920 B
__global__ __launch_bounds__(256, 2) void hmma_gemm_kernel(
    const __nv_bfloat16* __restrict__ Ah, const __nv_bfloat16* __restrict__ Al, long long sA,
    const __nv_bfloat16* __restrict__ Bh, const __nv_bfloat16* __restrict__ Bl, long long sB,
    float* __restrict__ C, int ldc, long long sC,
    int K, float alpha, int mode,
    const float* __restrict__ bias,
    const float* __restrict__ resid,
    const float* __restrict__ gate,
    __nv_bfloat16* __restrict__ outH,
    __nv_bfloat16* __restrict__ outL) {
    extern __shared__ __align__(16) __nv_bfloat16 smem[];

    const long long bz = blockIdx.z;
    Ah += bz * sA; Al += bz * sA;
    Bh += bz * sB; Bl += bz * sB;

    const int tid = threadIdx.x;
    const int wid = tid >> 5, lane = tid & 31;
    const int m0 = blockIdx.x * 128, n0 = blockIdx.y * 128;
    const int wm = (wid >> 2) * 64, wn = (wid & 3) * 32;

    float acc[4][4][4];
#pragma unroll
    for (int mt = 0; mt < 4; mt++)
#pragma unroll
        for (int nt = 0; nt < 4; nt++)
#pragma unroll
            for (int r = 0; r < 4; r++) acc[mt][nt][r] = 0.0f;

    const int lr = tid >> 2;          // 0..63
    const int lc = (tid & 3) * 8;     // 0,8,16,24 (bf16 elems, 16B chunks)
    const int nk = K / KC;

    // prologue: stage 0
    {
        __nv_bfloat16* sb = smem;
#pragma unroll
        for (int i = 0; i < 2; i++) {
            int row = lr + i * 64;
            int so = row * TSTR + lc;
            cp_async16(sb + so,                  Ah + (size_t)(m0 + row) * K + lc);
            cp_async16(sb + TILE_ELEMS + so,     Al + (size_t)(m0 + row) * K + lc);
            cp_async16(sb + 2 * TILE_ELEMS + so, Bh + (size_t)(n0 + row) * K + lc);
            cp_async16(sb + 3 * TILE_ELEMS + so, Bl + (size_t)(n0 + row) * K + lc);
        }
        asm volatile("cp.async.commit_group;" ::: "memory");
    }

    for (int it = 0; it < nk; it++) {
        asm volatile("cp.async.wait_group 0;" ::: "memory");
        __syncthreads();
        if (it + 1 < nk) {
            int kc = (it + 1) * KC;
            __nv_bfloat16* sb = smem + ((it + 1) & 1) * STAGE_ELEMS;
#pragma unroll
            for (int i = 0; i < 2; i++) {
                int row = lr + i * 64;
                int so = row * TSTR + lc;
                cp_async16(sb + so,                  Ah + (size_t)(m0 + row) * K + kc + lc);
                cp_async16(sb + TILE_ELEMS + so,     Al + (size_t)(m0 + row) * K + kc + lc);
                cp_async16(sb + 2 * TILE_ELEMS + so, Bh + (size_t)(n0 + row) * K + kc + lc);
                cp_async16(sb + 3 * TILE_ELEMS + so, Bl + (size_t)(n0 + row) * K + kc + lc);
            }
            asm volatile("cp.async.commit_group;" ::: "memory");
        }
        const __nv_bfloat16* sAh = smem + (it & 1) * STAGE_ELEMS;
        const __nv_bfloat16* sAl = sAh + TILE_ELEMS;
        const __nv_bfloat16* sBh = sAh + 2 * TILE_ELEMS;
        const __nv_bfloat16* sBl = sAh + 3 * TILE_ELEMS;

#pragma unroll
        for (int ks = 0; ks < 2; ks++) {
            const int k0 = ks * 16;
            const int ar = lane >> 2, ak = (lane & 3) * 2;
            uint32_t ah[4][4], bh[4][2], xl[4][4];
#pragma unroll
            for (int mt = 0; mt < 4; mt++) {
                int base = (wm + mt * 16 + ar) * TSTR + k0 + ak;
                ah[mt][0] = *(const uint32_t*)&sAh[base];
                ah[mt][1] = *(const uint32_t*)&sAh[base + 8 * TSTR];
                ah[mt][2] = *(const uint32_t*)&sAh[base + 8];
                ah[mt][3] = *(const uint32_t*)&sAh[base + 8 * TSTR + 8];
            }
#pragma unroll
            for (int nt = 0; nt < 4; nt++) {
                int base = (wn + nt * 8 + ar) * TSTR + k0 + ak;
                bh[nt][0] = *(const uint32_t*)&sBh[base];
                bh[nt][1] = *(const uint32_t*)&sBh[base + 8];
            }
#pragma unroll
            for (int mt = 0; mt < 4; mt++)
#pragma unroll
                for (int nt = 0; nt < 4; nt++) mma16816(acc[mt][nt], ah[mt], bh[nt]);
#pragma unroll
            for (int mt = 0; mt < 4; mt++) {
                int base = (wm + mt * 16 + ar) * TSTR + k0 + ak;
                xl[mt][0] = *(const uint32_t*)&sAl[base];
                xl[mt][1] = *(const uint32_t*)&sAl[base + 8 * TSTR];
                xl[mt][2] = *(const uint32_t*)&sAl[base + 8];
                xl[mt][3] = *(const uint32_t*)&sAl[base + 8 * TSTR + 8];
            }
#pragma unroll
            for (int mt = 0; mt < 4; mt++)
#pragma unroll
                for (int nt = 0; nt < 4; nt++) mma16816(acc[mt][nt], xl[mt], bh[nt]);
            uint32_t bl[4][2];
#pragma unroll
            for (int nt = 0; nt < 4; nt++) {
                int base = (wn + nt * 8 + ar) * TSTR + k0 + ak;
                bl[nt][0] = *(const uint32_t*)&sBl[base];
                bl[nt][1] = *(const uint32_t*)&sBl[base + 8];
            }
#pragma unroll
            for (int mt = 0; mt < 4; mt++)
#pragma unroll
                for (int nt = 0; nt < 4; nt++) mma16816(acc[mt][nt], ah[mt], bl[nt]);
        }
    }

    // epilogue
#pragma unroll
    for (int mt = 0; mt < 4; mt++) {
#pragma unroll
        for (int h = 0; h < 2; h++) {
            long long m = (long long)m0 + wm + mt * 16 + (lane >> 2) + h * 8;
            long long crow = bz * sC + m * ldc;
#pragma unroll
            for (int nt = 0; nt < 4; nt++) {
                int n = n0 + wn + nt * 8 + (lane & 3) * 2;
                float vx = acc[mt][nt][h * 2 + 0];
                float vy = acc[mt][nt][h * 2 + 1];
                if (mode == 0) {
                    vx *= alpha; vy *= alpha;
                    float2 o; o.x = vx; o.y = vy;
                    *(float2*)(C + crow + n) = o;
                } else if (mode == 3) {
                    __nv_bfloat162 hp, lp;
                    hp.x = __float2bfloat16(vx);
                    hp.y = __float2bfloat16(vy);
                    lp.x = __float2bfloat16(vx - __bfloat162float(hp.x));
                    lp.y = __float2bfloat16(vy - __bfloat162float(hp.y));
                    *(uint32_t*)(outH + crow + n) = *(uint32_t*)&hp;
                    *(uint32_t*)(outL + crow + n) = *(uint32_t*)&lp;
                } else {
                    vx += bias[n]; vy += bias[n + 1];
                    if (mode == 2) {
                        float2 xv = *(const float2*)(resid + m * ldc + n);
                        vx = fmaf(gate[n],     vx, xv.x);
                        vy = fmaf(gate[n + 1], vy, xv.y);
                    }
                    float2 o; o.x = vx; o.y = vy;
                    *(float2*)(C + crow + n) = o;
                }
            }
        }
    }
}

// =================== split / transpose prep kernels =========================
__global__ void split_kernel(const float* __restrict__ src,
                             __nv_bfloat16* __restrict__ dh,
                             __nv_bfloat16* __restrict__ dl) {
    size_t i = ((size_t)blockIdx.x * 256 + threadIdx.x) * 4;
    float4 v = *(const float4*)(src + i);
    __nv_bfloat162 hA, hB, lA, lB;
    hA.x = __float2bfloat16(v.x); hA.y = __float2bfloat16(v.y);
    hB.x = __float2bfloat16(v.z); hB.y = __float2bfloat16(v.w);
    lA.x = __float2bfloat16(v.x - __bfloat162float(hA.x));
    lA.y = __float2bfloat16(v.y - __bfloat162float(hA.y));
    lB.x = __float2bfloat16(v.z - __bfloat162float(hB.x));
    lB.y = __float2bfloat16(v.w - __bfloat162float(hB.y));
    uint2 uh, ul;
    uh.x = *(uint32_t*)&hA; uh.y = *(uint32_t*)&hB;
    ul.x = *(uint32_t*)&lA; ul.y = *(uint32_t*)&lB;
    *(uint2*)(dh + i) = uh;
    *(uint2*)(dl + i) = ul;
}

// src fp32 [R, Cc] -> dh/dl bf16 [Cc, R] (transposed, split)
__global__ void transpose_split_kernel(const float* __restrict__ src, int R, int Cc,
                                       __nv_bfloat16* __restrict__ dh,
                                       __nv_bfloat16* __restrict__ dl) {
    __shared__ float t[32][33];
    int c0 = blockIdx.x * 32, r0 = blockIdx.y * 32;
    int tx = threadIdx.x, ty = threadIdx.y;
#pragma unroll
    for (int i = 0; i < 4; i++)
        t[ty + 8 * i][tx] = src[(size_t)(r0 + ty + 8 * i) * Cc + c0 + tx];
    __syncthreads();
#pragma unroll
    for (int i = 0; i < 4; i++) {
        float v = t[tx][ty + 8 * i];
        __nv_bfloat16 h = __float2bfloat16(v);
        size_t o = (size_t)(c0 + ty + 8 * i) * R + r0 + tx;
        dh[o] = h;
        dl[o] = __float2bfloat16(v - __bfloat162float(h));
    }
}

// per-head: d_v [h][SEQ][HD] fp32 -> d_vt [h][HD][SEQ] bf16 split
__global__ void transpose_split_v_kernel() {
    __shared__ float t[32][33];
    int h = blockIdx.z;
    int c0 = blockIdx.x * 32;   // d
    int r0 = blockIdx.y * 32;   // seq
    int tx = threadIdx.x, ty = threadIdx.y;
    const float* src = d_v + (size_t)h * SEQ * HD;
#pragma unroll
    for (int i = 0; i < 4; i++)
        t[ty + 8 * i][tx] = src[(size_t)(r0 + ty + 8 * i) * HD + c0 + tx];
    __syncthreads();
    size_t base = (size_t)h * HD * SEQ;
#pragma unroll
    for (int i = 0; i < 4; i++) {
        float v = t[tx][ty + 8 * i];
        __nv_bfloat16 hh = __float2bfloat16(v);
        size_t o = base + (size_t)(c0 + ty + 8 * i) * SEQ + r0 + tx;
        d_vth[o] = hh;
        d_vtl[o] = __float2bfloat16(v - __bfloat162float(hh));
    }
}

// =================== small kernels =========================================
__global__ void mod_gemv_kernel(const float* __restrict__ vec,
                                const float* __restrict__ mod_w,
                                const float* __restrict__ mod_b,
                                float* __restrict__ mod) {
    __shared__ float sv[HIDDEN];
    for (int i = threadIdx.x; i < HIDDEN; i += 256) {
        float v = vec[i];
        sv[i] = v / (1.0f + expf(-v));
    }
    __syncthreads();
    int j = blockIdx.x * 256 + threadIdx.x;
    const float* wp = mod_w + j;
    float acc = 0.0f;
#pragma unroll 8
    for (int k = 0; k < HIDDEN; k++) acc = fmaf(sv[k], wp[(size_t)k * MODN], acc);
    mod[j] = acc + mod_b[j];
}

__global__ void ln_mod_kernel(const float* __restrict__ x) {
    int row = blockIdx.x;
    const float* xr = x + (size_t)row * HIDDEN;
    __shared__ float r1[256], r2[256];
    float s = 0.0f, s2 = 0.0f;
    for (int i = threadIdx.x; i < HIDDEN; i += 256) {
        float v = xr[i];
        s += v;
        s2 = fmaf(v, v, s2);
    }
    r1[threadIdx.x] = s; r2[threadIdx.x] = s2;
    __syncthreads();
    for (int o = 128; o > 0; o >>= 1) {
        if (threadIdx.x < o) { r1[threadIdx.x] += r1[threadIdx.x + o]; r2[threadIdx.x] += r2[threadIdx.x + o]; }
        __syncthreads();
    }
    float mu  = r1[0] * (1.0f / HIDDEN);
    float var = r2[0] * (1.0f / HIDDEN) - mu * mu;
    float inv = rsqrtf(var + 1e-6f);
    float* orow = d_xmod + (size_t)row * HIDDEN;
    for (int i = threadIdx.x; i < HIDDEN; i += 256) {
        float sc = 1.0f + d_mod[HIDDEN + i];
        orow[i] = (xr[i] - mu) * inv * sc + d_mod[i];
    }
}

// split qkv, RMSNorm q/k, RoPE; q/k -> bf16 split [h][l][d], v fp32 [h][l][d]
__global__ void qkv_prep_kernel(const float* __restrict__ pe,
                                const float* __restrict__ qnw,
                                const float* __restrict__ knw) {
    int wg = blockIdx.x * 8 + (threadIdx.x >> 5);
    int lane = threadIdx.x & 31;
    int l = wg / NH, hd = wg % NH;
    const float* base = d_h + (size_t)l * W1N + hd * HD + lane * 4;
    float4 qv = *reinterpret_cast<const float4*>(base);
    float4 kv = *reinterpret_cast<const float4*>(base + HIDDEN);
    float4 vv = *reinterpret_cast<const float4*>(base + 2 * HIDDEN);

    float sq = qv.x * qv.x + qv.y * qv.y + qv.z * qv.z + qv.w * qv.w;
    float sk = kv.x * kv.x + kv.y * kv.y + kv.z * kv.z + kv.w * kv.w;
#pragma unroll
    for (int o = 16; o > 0; o >>= 1) {
        sq += __shfl_xor_sync(0xffffffffu, sq, o);
        sk += __shfl_xor_sync(0xffffffffu, sk, o);
    }
    float rq = rsqrtf(sq * (1.0f / HD) + 1e-6f);
    float rk = rsqrtf(sk * (1.0f / HD) + 1e-6f);
    float4 wq = *reinterpret_cast<const float4*>(qnw + lane * 4);
    float4 wk = *reinterpret_cast<const float4*>(knw + lane * 4);
    float q0 = qv.x * rq * wq.x, q1 = qv.y * rq * wq.y, q2 = qv.z * rq * wq.z, q3 = qv.w * rq * wq.w;
    float k0 = kv.x * rk * wk.x, k1 = kv.y * rk * wk.y, k2 = kv.z * rk * wk.z, k3 = kv.w * rk * wk.w;

    const float* pep = pe + (size_t)l * 256 + lane * 8;
    float4 p0 = *reinterpret_cast<const float4*>(pep);
    float4 p1 = *reinterpret_cast<const float4*>(pep + 4);
    float4 qo, ko;
    qo.x = p0.x * q0 + p0.y * q1;  qo.y = p0.z * q0 + p0.w * q1;
    qo.z = p1.x * q2 + p1.y * q3;  qo.w = p1.z * q2 + p1.w * q3;
    ko.x = p0.x * k0 + p0.y * k1;  ko.y = p0.z * k0 + p0.w * k1;
    ko.z = p1.x * k2 + p1.y * k3;  ko.w = p1.z * k2 + p1.w * k3;

    size_t o = ((size_t)hd * SEQ + l) * HD + lane * 4;
    // q/k split bf16
    __nv_bfloat162 hA, hB, lA, lB;
    uint2 uh, ul;
    hA.x = __float2bfloat16(qo.x); hA.y = __float2bfloat16(qo.y);
    hB.x = __float2bfloat16(qo.z); hB.y = __float2bfloat16(qo.w);
    lA.x = __float2bfloat16(qo.x - __bfloat162float(hA.x));
    lA.y = __float2bfloat16(qo.y - __bfloat162float(hA.y));
    lB.x = __float2bfloat16(qo.z - __bfloat162float(hB.x));
    lB.y = __float2bfloat16(qo.w - __bfloat162float(hB.y));
    uh.x = *(uint32_t*)&hA; uh.y = *(uint32_t*)&hB;
    ul.x = *(uint32_t*)&lA; ul.y = *(uint32_t*)&lB;
    *(uint2*)(d_qh + o) = uh; *(uint2*)(d_ql + o) = ul;

    hA.x = __float2bfloat16(ko.x); hA.y = __float2bfloat16(ko.y);
    hB.x = __float2bfloat16(ko.z); hB.y = __float2bfloat16(ko.w);
    lA.x = __float2bfloat16(ko.x - __bfloat162float(hA.x));
    lA.y = __float2bfloat16(ko.y - __bfloat162float(hA.y));
    lB.x = __float2bfloat16(ko.z - __bfloat162float(hB.x));
    lB.y = __float2bfloat16(ko.w - __bfloat162float(hB.y));
    uh.x = *(uint32_t*)&hA; uh.y = *(uint32_t*)&hB;
    ul.x = *(uint32_t*)&lA; ul.y = *(uint32_t*)&lB;
    *(uint2*)(d_kh + o) = uh; *(uint2*)(d_kl + o) = ul;

    *reinterpret_cast<float4*>(d_v + o) = vv;
}

// row softmax over d_s; outputs split bf16 probs to d_sh/d_sl
__global__ void softmax_split_kernel() {
    size_t rowoff = (size_t)blockIdx.x * SEQ;
    float* row = d_s + rowoff;
    int tid = threadIdx.x;
    float v[8];
    float m = -1e30f;
#pragma unroll
    for (int j = 0; j < 8; j++) { v[j] = row[tid + j * 256]; m = fmaxf(m, v[j]); }
    __shared__ float red[256];
    red[tid] = m;
    __syncthreads();
    for (int o = 128; o > 0; o >>= 1) {
        if (tid < o) red[tid] = fmaxf(red[tid], red[tid + o]);
        __syncthreads();
    }
    m = red[0];
    __syncthreads();
    float s = 0.0f;
#pragma unroll
    for (int j = 0; j < 8; j++) { v[j] = __expf(v[j] - m); s += v[j]; }
    red[tid] = s;
    __syncthreads();
    for (int o = 128; o > 0; o >>= 1) {
        if (tid < o) red[tid] += red[tid + o];
        __syncthreads();
    }
    float inv = 1.0f / red[0];
#pragma unroll
    for (int j = 0; j < 8; j++) {
        float p = v[j] * inv;
        __nv_bfloat16 h = __float2bfloat16(p);
        d_sh[rowoff + tid + j * 256] = h;
        d_sl[rowoff + tid + j * 256] = __float2bfloat16(p - __bfloat162float(h));
    }
}

// gelu(mlp half of h) -> split bf16 directly into a2 [:, HIDDEN:]
__global__ void gelu_split_kernel() {
    size_t g = ((size_t)blockIdx.x * 256 + threadIdx.x) * 2;  // over SEQ*MLPD, pairs
    size_t r = g / MLPD;
    int j = (int)(g % MLPD);
    float2 xv = *(const float2*)(d_h + r * W1N + 3 * HIDDEN + j);
    float t0 = tanhf(0.7978845608028654f * (xv.x + 0.044715f * xv.x * xv.x * xv.x));
    float t1 = tanhf(0.7978845608028654f * (xv.y + 0.044715f * xv.y * xv.y * xv.y));
    float g0 = 0.5f * xv.x * (1.0f + t0);
    float g1 = 0.5f * xv.y * (1.0f + t1);
    __nv_bfloat162 hp, lp;
    hp.x = __float2bfloat16(g0); hp.y = __float2bfloat16(g1);
    lp.x = __float2bfloat16(g0 - __bfloat162float(hp.x));
    lp.y = __float2bfloat16(g1 - __bfloat162float(hp.y));
    size_t o = r * CATN + HIDDEN + j;
    *(uint32_t*)(d_a2h + o) = *(uint32_t*)&hp;
    *(uint32_t*)(d_a2l + o) = *(uint32_t*)&lp;
}

// =================== driver =================================================
extern "C" void kernel_launch(void* const* d_in, const int* in_sizes, int n_in,
                              void* d_out, int out_size) {
    const float* x     = (const float*)d_in[0];
    const float* vec   = (const float*)d_in[1];
    const float* pe    = (const float*)d_in[2];
    const float* w1    = (const float*)d_in[3];
    const float* b1    = (const float*)d_in[4];
    const float* w2    = (const float*)d_in[5];
    const float* b2    = (const float*)d_in[6];
    const float* mod_w = (const float*)d_in[7];
    const float* mod_b = (const float*)d_in[8];
    const float* qnw   = (const float*)d_in[9];
    const float* knw   = (const float*)d_in[10];
    float* out = (float*)d_out;

    float *p_mod, *p_xmod, *p_h, *p_s;
    __nv_bfloat16 *p_a1h, *p_a1l, *p_a2h, *p_a2l, *p_w1th, *p_w1tl, *p_w2th, *p_w2tl;
    __nv_bfloat16 *p_qh, *p_ql, *p_kh, *p_kl, *p_vth, *p_vtl, *p_sh, *p_sl;
    cudaGetSymbolAddress((void**)&p_mod,  d_mod);
    cudaGetSymbolAddress((void**)&p_xmod, d_xmod);
    cudaGetSymbolAddress((void**)&p_h,    d_h);
    cudaGetSymbolAddress((void**)&p_s,    d_s);
    cudaGetSymbolAddress((void**)&p_a1h,  d_a1h);
    cudaGetSymbolAddress((void**)&p_a1l,  d_a1l);
    cudaGetSymbolAddress((void**)&p_a2h,  d_a2h);
    cudaGetSymbolAddress((void**)&p_a2l,  d_a2l);
    cudaGetSymbolAddress((void**)&p_w1th, d_w1th);
    cudaGetSymbolAddress((void**)&p_w1tl, d_w1tl);
    cudaGetSymbolAddress((void**)&p_w2th, d_w2th);
    cudaGetSymbolAddress((void**)&p_w2tl, d_w2tl);
    cudaGetSymbolAddress((void**)&p_qh,   d_qh);
    cudaGetSymbolAddress((void**)&p_ql,   d_ql);
    cudaGetSymbolAddress((void**)&p_kh,   d_kh);
    cudaGetSymbolAddress((void**)&p_kl,   d_kl);
    cudaGetSymbolAddress((void**)&p_vth,  d_vth);
    cudaGetSymbolAddress((void**)&p_vtl,  d_vtl);
    cudaGetSymbolAddress((void**)&p_sh,   d_sh);
    cudaGetSymbolAddress((void**)&p_sl,   d_sl);

    cudaFuncSetAttribute(hmma_gemm_kernel, cudaFuncAttributeMaxDynamicSharedMemorySize,
                         HMMA_SMEM_BYTES);

    const float sc = 0.08838834764831845f;

    // 1) modulation + LN
    mod_gemv_kernel<<<MODN / 256, 256>>>(vec, mod_w, mod_b, p_mod);
    ln_mod_kernel<<<SEQ, 256>>>(x);
    // 2) operand prep for GEMM1 (+ weight transposes)
    split_kernel<<<(SEQ * HIDDEN) / 1024, 256>>>(p_xmod, p_a1h, p_a1l);
    transpose_split_kernel<<<dim3(W1N / 32, HIDDEN / 32), dim3(32, 8)>>>(w1, HIDDEN, W1N, p_w1th, p_w1tl);
    transpose_split_kernel<<<dim3(HIDDEN / 32, CATN / 32), dim3(32, 8)>>>(w2, CATN, HIDDEN, p_w2th, p_w2tl);
    // 3) GEMM1: h = x_mod @ w1 + b1
    hmma_gemm_kernel<<<dim3(SEQ / 128, W1N / 128, 1), 256, HMMA_SMEM_BYTES>>>(
        p_a1h, p_a1l, 0, p_w1th, p_w1tl, 0, p_h, W1N, 0,
        HIDDEN, 1.0f, 1, b1, nullptr, nullptr, nullptr, nullptr);
    // 4) qkv prep (q/k split bf16, v fp32)
    qkv_prep_kernel<<<SEQ * NH / 8, 256>>>(pe, qnw, knw);
    // 5) v transpose-split
    transpose_split_v_kernel<<<dim3(HD / 32, SEQ / 32, NH), dim3(32, 8)>>>();
    // 6) scores = (q @ k^T) * sc  (HMMA, batched over heads)
    hmma_gemm_kernel<<<dim3(SEQ / 128, SEQ / 128, NH), 256, HMMA_SMEM_BYTES>>>(
        p_qh, p_ql, (long long)SEQ * HD, p_kh, p_kl, (long long)SEQ * HD,
        p_s, SEQ, (long long)SEQ * SEQ,
        HD, sc, 0, nullptr, nullptr, nullptr, nullptr, nullptr);
    // 7) softmax + split probs
    softmax_split_kernel<<<NH * SEQ, 256>>>();
    // 8) attn = probs @ v -> split directly into a2[:, h*HD:(h+1)*HD]
    hmma_gemm_kernel<<<dim3(SEQ / 128, 1, NH), 256, HMMA_SMEM_BYTES>>>(
        p_sh, p_sl, (long long)SEQ * SEQ, p_vth, p_vtl, (long long)HD * SEQ,
        nullptr, CATN, (long long)HD,
        SEQ, 1.0f, 3, nullptr, nullptr, nullptr, p_a2h, p_a2l);
    // 9) gelu -> split directly into a2[:, HIDDEN:]
    gelu_split_kernel<<<(SEQ * MLPD) / 512, 256>>>();
    // 10) GEMM2: out = x + gate * (cat @ w2 + b2)
    hmma_gemm_kernel<<<dim3(SEQ / 128, HIDDEN / 128, 1), 256, HMMA_SMEM_BYTES>>>(
        p_a2h, p_a2l, 0, p_w2th, p_w2tl, 0, out, HIDDEN, 0,
        CATN, 1.0f, 2, b2, x, p_mod + 2 * HIDDEN, nullptr, nullptr);
}